// round 13
// baseline (speedup 1.0000x reference)
#include <cuda_runtime.h>
#include <cuda_bf16.h>
#include <math.h>
#include <stdint.h>

#define BATCH     16
#define MEM_DIM   172
#define TOK       4096
#define TIME_DIM  100
#define LEN_TOK   512
#define NROWS     44

// g_wh/g_wl row layout: [0,176) = W1 (pad rows 0), [176,352) = W2, [352,464) = Wt
#define WROWS     464

__device__ __align__(16) __nv_bfloat16 g_wh[WROWS * TOK];
__device__ __align__(16) __nv_bfloat16 g_wl[WROWS * TOK];
__device__ __align__(16) float g_res[BATCH * NROWS * TOK];

// ---------------------------------------------------------------------------
__device__ __forceinline__ uint32_t s2u(const void* p) {
    return (uint32_t)__cvta_generic_to_shared(p);
}
__device__ __forceinline__ void cp16(uint32_t dst, const void* src) {
    asm volatile("cp.async.cg.shared.global [%0], [%1], 16;" :: "r"(dst), "l"(src));
}
__device__ __forceinline__ void cp_commit() { asm volatile("cp.async.commit_group;"); }
template<int N> __device__ __forceinline__ void cp_wait() {
    asm volatile("cp.async.wait_group %0;" :: "n"(N) : "memory");
}
__device__ __forceinline__ void mma_bf16(float& d0, float& d1, float& d2, float& d3,
                                         uint32_t a0, uint32_t a1, uint32_t a2, uint32_t a3,
                                         uint32_t b0, uint32_t b1)
{
    asm volatile(
        "mma.sync.aligned.m16n8k16.row.col.f32.bf16.bf16.f32 "
        "{%0,%1,%2,%3}, {%4,%5,%6,%7}, {%8,%9}, {%0,%1,%2,%3};"
        : "+f"(d0), "+f"(d1), "+f"(d2), "+f"(d3)
        : "r"(a0), "r"(a1), "r"(a2), "r"(a3), "r"(b0), "r"(b1));
}
__device__ __forceinline__ void ldsm_x4(uint32_t& r0, uint32_t& r1, uint32_t& r2,
                                        uint32_t& r3, uint32_t addr) {
    asm volatile("ldmatrix.sync.aligned.m8n8.x4.shared.b16 {%0,%1,%2,%3}, [%4];"
                 : "=r"(r0), "=r"(r1), "=r"(r2), "=r"(r3) : "r"(addr));
}
__device__ __forceinline__ void ldsm_x2t(uint32_t& r0, uint32_t& r1, uint32_t addr) {
    asm volatile("ldmatrix.sync.aligned.m8n8.x2.trans.shared.b16 {%0,%1}, [%2];"
                 : "=r"(r0), "=r"(r1) : "r"(addr));
}

// ---------------------------------------------------------------------------
// Prep: split W1/W2/Wt into bf16 hi/lo. Vectorized: 8 elements per thread.
// ---------------------------------------------------------------------------
__global__ void __launch_bounds__(256)
k_prep(const float* __restrict__ W1, const float* __restrict__ W2,
       const float* __restrict__ Wt)
{
    int i = blockIdx.x * 256 + threadIdx.x;
    if (i >= WROWS * TOK / 8) return;
    int row = i >> 9;                 // 512 8-col groups per row
    int c8  = (i & 511) << 3;

    const float* src = nullptr;
    if (row < 176)      { if (row < 172)            src = W1 + (size_t)row * TOK + c8; }
    else if (row < 352) { int k = row - 176; if (k < 172) src = W2 + (size_t)k * TOK + c8; }
    else                { int k = row - 352; if (k < 100) src = Wt + (size_t)k * TOK + c8; }

    float v[8] = {0.f, 0.f, 0.f, 0.f, 0.f, 0.f, 0.f, 0.f};
    if (src) {
        float4 a = __ldg((const float4*)src);
        float4 b = __ldg((const float4*)(src + 4));
        v[0] = a.x; v[1] = a.y; v[2] = a.z; v[3] = a.w;
        v[4] = b.x; v[5] = b.y; v[6] = b.z; v[7] = b.w;
    }
    __align__(16) __nv_bfloat16 h[8], l[8];
#pragma unroll
    for (int j = 0; j < 8; j++) {
        h[j] = __float2bfloat16(v[j]);
        l[j] = __float2bfloat16(v[j] - __bfloat162float(h[j]));
    }
    *(uint4*)(g_wh + (size_t)row * TOK + c8) = *(uint4*)h;
    *(uint4*)(g_wl + (size_t)row * TOK + c8) = *(uint4*)l;
}

// ---------------------------------------------------------------------------
// Proj smem layout (bytes):
//   A region [0, 47104):
//     G1/G2: A1h@0, A1l@11776, A2h@23552, A2l@35328   (32x184 bf16, 368B rows)
//     G3 (reuse): Th@0, Tl@15360                       (64x120 bf16, 240B rows)
//   W stages: stg0@47104, stg1@63, each [hi 16x528B][lo 16x528B] = 16896 B
// ---------------------------------------------------------------------------
#define A_REGION_B 47104
#define WS_ROW_B   528
#define WSTG_B     (2 * 16 * WS_ROW_B)           // 16896
#define SMEMP_B    (A_REGION_B + 2 * WSTG_B)     // 80896

__device__ __forceinline__ void fill_wstage(char* stg, int krow0, int col0, int tid)
{
#pragma unroll
    for (int j = 0; j < 4; j++) {
        int c   = tid + 256 * j;            // 0..1023
        int mat = c >> 9;                   // 0 = hi, 1 = lo
        int r   = (c >> 5) & 15;
        int c16 = c & 31;
        const __nv_bfloat16* src = (mat ? g_wl : g_wh)
                                 + (size_t)(krow0 + r) * TOK + col0 + c16 * 8;
        cp16(s2u(stg + mat * (16 * WS_ROW_B) + r * WS_ROW_B + c16 * 16), src);
    }
}

// One GEMM: MT m16-tiles, NSTEP k16-steps. 3-product bf16 compensated.
// orow[mt] = g_res row index of this tile's row 0; nval[mt] = valid rows in tile.
template<int MT, int NSTEP>
__device__ __forceinline__ void run_gemm(
    char* stg0, char* stg1,
    uint32_t aH, uint32_t aL, int astride_b,
    int wrow0, int col0,
    const size_t* orow, const int* nval,
    const float* __restrict__ bias, int tid)
{
    const int lane = tid & 31;
    const int wid  = tid >> 5;
    const int n0   = wid * 32;              // 32 cols per warp
    const int g    = lane >> 2;
    const int tg   = lane & 3;
    const int arow = lane & 15;
    const int acol = (lane >> 4) << 3;
    const int brow = lane & 15;

    float acc[MT][4][4];
#pragma unroll
    for (int mt = 0; mt < MT; mt++)
#pragma unroll
        for (int j = 0; j < 4; j++)
#pragma unroll
            for (int q = 0; q < 4; q++) acc[mt][j][q] = 0.f;

    fill_wstage(stg0, wrow0, col0, tid);
    cp_commit();

    for (int s = 0; s < NSTEP; s++) {
        if (s + 1 < NSTEP) {
            fill_wstage((s & 1) ? stg0 : stg1, wrow0 + (s + 1) * 16, col0, tid);
            cp_commit();
            cp_wait<1>();
        } else {
            cp_wait<0>();
        }
        __syncthreads();

        char* st = (s & 1) ? stg1 : stg0;
        const uint32_t st_s = s2u(st);
        const int k0 = s * 16;

        uint32_t bh[4][2], bl[4][2];
#pragma unroll
        for (int j = 0; j < 4; j++) {
            uint32_t baddr = st_s + brow * WS_ROW_B + (n0 + j * 8) * 2;
            ldsm_x2t(bh[j][0], bh[j][1], baddr);
            ldsm_x2t(bl[j][0], bl[j][1], baddr + 16 * WS_ROW_B);
        }
#pragma unroll
        for (int mt = 0; mt < MT; mt++) {
            uint32_t ah0, ah1, ah2, ah3, al0, al1, al2, al3;
            ldsm_x4(ah0, ah1, ah2, ah3,
                    aH + (mt * 16 + arow) * astride_b + (k0 + acol) * 2);
            ldsm_x4(al0, al1, al2, al3,
                    aL + (mt * 16 + arow) * astride_b + (k0 + acol) * 2);
#pragma unroll
            for (int j = 0; j < 4; j++) {
                mma_bf16(acc[mt][j][0], acc[mt][j][1], acc[mt][j][2], acc[mt][j][3],
                         ah0, ah1, ah2, ah3, bh[j][0], bh[j][1]);
                mma_bf16(acc[mt][j][0], acc[mt][j][1], acc[mt][j][2], acc[mt][j][3],
                         ah0, ah1, ah2, ah3, bl[j][0], bl[j][1]);
                mma_bf16(acc[mt][j][0], acc[mt][j][1], acc[mt][j][2], acc[mt][j][3],
                         al0, al1, al2, al3, bh[j][0], bh[j][1]);
            }
        }
        __syncthreads();
    }

    // writeback with bias
#pragma unroll
    for (int mt = 0; mt < MT; mt++) {
        float* base = g_res + orow[mt] * TOK + col0;
        const int r0 = g;
#pragma unroll
        for (int j = 0; j < 4; j++) {
            const int c = n0 + j * 8 + tg * 2;
            float bv0 = __ldg(&bias[col0 + c]);
            float bv1 = __ldg(&bias[col0 + c + 1]);
            if (r0 < nval[mt]) {
                float2 v = make_float2(acc[mt][j][0] + bv0, acc[mt][j][1] + bv1);
                *(float2*)(base + (size_t)r0 * TOK + c) = v;
            }
            if (r0 + 8 < nval[mt]) {
                float2 v = make_float2(acc[mt][j][2] + bv0, acc[mt][j][3] + bv1);
                *(float2*)(base + (size_t)(r0 + 8) * TOK + c) = v;
            }
        }
    }
}

// ---------------------------------------------------------------------------
// Proj: grid (8 batch-pairs, 16 n-tiles of 256 cols) = 128 CTAs (single wave),
// block 256. Each CTA handles 2 batches; W stages shared across the pair.
// ---------------------------------------------------------------------------
__global__ void __launch_bounds__(256)
k_proj(const float* __restrict__ memory,
       const int*   __restrict__ src_nodes,
       const int*   __restrict__ dst_nodes,
       const int*   __restrict__ src_nei,
       const int*   __restrict__ dst_nei,
       const float* __restrict__ timestamps,
       const float* __restrict__ se,
       const float* __restrict__ de,
       const float* __restrict__ bias1,
       const float* __restrict__ bias2,
       const float* __restrict__ biast,
       const float* __restrict__ w_time,
       const float* __restrict__ phase)
{
    extern __shared__ __align__(16) char sm[];
    char* Areg = sm;
    char* stg0 = sm + A_REGION_B;
    char* stg1 = stg0 + WSTG_B;

    const int bb0  = blockIdx.x * 2;       // batch pair (bb0, bb0+1)
    const int tile = blockIdx.y;
    const int col0 = tile * 256;
    const int tid  = threadIdx.x;

    // ---- stage A1/A2 hi/lo for both batches (32 rows x 176 cols each) ----
    // rows 0-10 = batch bb0 (valid), 11-15 zero, 16-26 = bb0+1, 27-31 zero
    for (int i = tid; i < 2 * 32 * 176; i += 256) {
        int m  = i / (32 * 176);            // 0 = A1, 1 = A2
        int rr = (i / 176) & 31;
        int k  = i % 176;
        int r  = rr & 15;
        float a = 0.f;
        if (r < 11 && k < 172) {
            int bb = bb0 + (rr >> 4);
            int node;
            if (m == 0) node = (r == 0) ? src_nodes[bb] : dst_nei[bb * 10 + r - 1];
            else        node = (r == 0) ? dst_nodes[bb] : src_nei[bb * 10 + r - 1];
            a = memory[(size_t)node * MEM_DIM + k];
        }
        __nv_bfloat16 h = __float2bfloat16(a);
        __nv_bfloat16 l = __float2bfloat16(a - __bfloat162float(h));
        __nv_bfloat16* Ah = (__nv_bfloat16*)(Areg + m * 23552);
        __nv_bfloat16* Al = (__nv_bfloat16*)(Areg + m * 23552 + 11776);
        Ah[rr * 184 + k] = h;
        Al[rr * 184 + k] = l;
    }
    // (sync provided by first in-loop barrier of G1)

    const uint32_t A1h = s2u(Areg),          A1l = s2u(Areg + 11776);
    const uint32_t A2h = s2u(Areg + 23552),  A2l = s2u(Areg + 35328);

    {
        size_t orow[2] = {(size_t)bb0 * NROWS, (size_t)(bb0 + 1) * NROWS};
        int    nv[2]   = {11, 11};
        run_gemm<2, 11>(stg0, stg1, A1h, A1l, 368, 0,   col0, orow, nv, bias1, tid);
        orow[0] += 11; orow[1] += 11;
        run_gemm<2, 11>(stg0, stg1, A2h, A2l, 368, 176, col0, orow, nv, bias2, tid);
    }

    // ---- stage tenc hi/lo for both batches (64 rows x 120-col stride) ----
    // rows 0-20 = bb0 tenc, 21-31 zero, 32-52 = bb0+1, 53-63 zero
    __syncthreads();
    for (int i = tid; i < 64 * 120; i += 256) {
        int rr = i / 120;
        int k  = i % 120;
        int r  = rr & 31;
        float v = 0.f;
        if (r < 21 && k < 100) {
            int bb = bb0 + (rr >> 5);
            float t0 = timestamps[bb];
            float delta;
            if (r == 0)      delta = 0.f;
            else if (r < 11) delta = t0 - se[bb * 10 + r - 1];
            else             delta = t0 - de[bb * 10 + r - 11];
            v = cosf(delta * w_time[k] + phase[k]);
        }
        __nv_bfloat16 h = __float2bfloat16(v);
        __nv_bfloat16 l = __float2bfloat16(v - __bfloat162float(h));
        ((__nv_bfloat16*)Areg)[rr * 120 + k] = h;
        ((__nv_bfloat16*)(Areg + 15360))[rr * 120 + k] = l;
    }

    const uint32_t Th = s2u(Areg), Tl = s2u(Areg + 15360);
    {
        size_t orow[4] = {(size_t)bb0 * NROWS + 22, (size_t)bb0 * NROWS + 38,
                          (size_t)(bb0 + 1) * NROWS + 22, (size_t)(bb0 + 1) * NROWS + 38};
        int    nv[4]   = {16, 5, 16, 5};
        run_gemm<4, 7>(stg0, stg1, Th, Tl, 240, 352, col0, orow, nv, biast, tid);
    }
}

// ---------------------------------------------------------------------------
// Scat (proven R9): grid (16 b, 16 tiles of 256 cols, 25 runs), block 256.
// ---------------------------------------------------------------------------
__global__ void __launch_bounds__(256)
k_scat(float* __restrict__ out)
{
    const int b    = blockIdx.x;
    const int tile = blockIdx.y;
    const int z    = blockIdx.z;
    const int tid  = threadIdx.x;
    const int lane = tid & 63;
    const int sub  = tid >> 6;

    int t0, n, rS, rD, rT;
    if (z < 10)       { t0 = 15 + 21 * z;  n = 21; rS = 0;  rD = 12 + z; rT = 23 + z; }
    else if (z < 20)  { int q = z - 10; t0 = 239 + 21 * q; n = 21; rS = 11; rD = 1 + q; rT = 33 + q; }
    else if (z == 20) { t0 = 0;   n = 15; rS = 0;  rD = 11; rT = 22; }
    else if (z == 21) { t0 = 225; n = 14; rS = 11; rD = 11; rT = 22; }
    else              { t0 = 449 + 21 * (z - 22); n = 21; rS = 0; rD = 11; rT = 22; }

    const float4* gresv = (const float4*)g_res;
    const int vrow = TOK / 4;
    const size_t rbase = (size_t)b * NROWS * vrow + tile * 64 + lane;
    const float4 vs = __ldg(&gresv[rbase + (size_t)rS * vrow]);
    const float4 vd = __ldg(&gresv[rbase + (size_t)rD * vrow]);
    const float4 vt = __ldg(&gresv[rbase + (size_t)rT * vrow]);

    float4* outv = (float4*)out;
    const size_t T = (size_t)BATCH * LEN_TOK * vrow;
    const size_t obase = (size_t)(b * LEN_TOK) * vrow + tile * 64 + lane;

    if (z == 20) {
        for (int i = sub; i < n; i += 4) {
            const int t = t0 + i;
            const size_t o = obase + (size_t)t * vrow;
            __stcs(&outv[o],         vs);
            __stcs(&outv[o + T],     (t == 0) ? vd : vs);
            __stcs(&outv[o + 2 * T], vt);
        }
    } else {
        for (int i = sub; i < n; i += 4) {
            const size_t o = obase + (size_t)(t0 + i) * vrow;
            __stcs(&outv[o],         vs);
            __stcs(&outv[o + T],     vd);
            __stcs(&outv[o + 2 * T], vt);
        }
    }
}

// ---------------------------------------------------------------------------
extern "C" void kernel_launch(void* const* d_in, const int* in_sizes, int n_in,
                              void* d_out, int out_size)
{
    const float* memory      = (const float*)d_in[0];
    const int*   src_nodes   = (const int*)  d_in[1];
    const int*   dst_nodes   = (const int*)  d_in[2];
    const int*   src_nei     = (const int*)  d_in[3];
    const int*   dst_nei     = (const int*)  d_in[4];
    const float* timestamps  = (const float*)d_in[5];
    const float* se          = (const float*)d_in[6];
    const float* de          = (const float*)d_in[7];
    const float* W1          = (const float*)d_in[8];
    const float* b1          = (const float*)d_in[9];
    const float* W2          = (const float*)d_in[10];
    const float* b2          = (const float*)d_in[11];
    const float* Wt          = (const float*)d_in[12];
    const float* bt          = (const float*)d_in[13];
    const float* w_time      = (const float*)d_in[14];
    const float* phase       = (const float*)d_in[15];
    float* out = (float*)d_out;

    cudaFuncSetAttribute(k_proj, cudaFuncAttributeMaxDynamicSharedMemorySize, SMEMP_B);

    k_prep<<<(WROWS * TOK / 8 + 255) / 256, 256>>>(W1, W2, Wt);
    k_proj<<<dim3(BATCH / 2, TOK / 256), 256, SMEMP_B>>>(memory, src_nodes, dst_nodes,
                                                         src_nei, dst_nei,
                                                         timestamps, se, de,
                                                         b1, b2, bt, w_time, phase);
    k_scat<<<dim3(BATCH, TOK / 256, 25), 256>>>(out);
}

// round 14
// speedup vs baseline: 1.0538x; 1.0538x over previous
#include <cuda_runtime.h>
#include <cuda_bf16.h>
#include <math.h>
#include <stdint.h>

#define BATCH     16
#define MEM_DIM   172
#define TOK       4096
#define TIME_DIM  100
#define LEN_TOK   512
#define NROWS     44

// g_wh/g_wl row layout: [0,176) = W1 (pad rows 0), [176,352) = W2, [352,464) = Wt
#define WROWS     464

__device__ __align__(16) __nv_bfloat16 g_wh[WROWS * TOK];
__device__ __align__(16) __nv_bfloat16 g_wl[WROWS * TOK];
__device__ __align__(16) float g_res[BATCH * NROWS * TOK];

// ---------------------------------------------------------------------------
__device__ __forceinline__ uint32_t s2u(const void* p) {
    return (uint32_t)__cvta_generic_to_shared(p);
}
__device__ __forceinline__ void cp16(uint32_t dst, const void* src) {
    asm volatile("cp.async.cg.shared.global [%0], [%1], 16;" :: "r"(dst), "l"(src));
}
__device__ __forceinline__ void cp_commit() { asm volatile("cp.async.commit_group;"); }
template<int N> __device__ __forceinline__ void cp_wait() {
    asm volatile("cp.async.wait_group %0;" :: "n"(N) : "memory");
}
__device__ __forceinline__ void mma_bf16(float& d0, float& d1, float& d2, float& d3,
                                         uint32_t a0, uint32_t a1, uint32_t a2, uint32_t a3,
                                         uint32_t b0, uint32_t b1)
{
    asm volatile(
        "mma.sync.aligned.m16n8k16.row.col.f32.bf16.bf16.f32 "
        "{%0,%1,%2,%3}, {%4,%5,%6,%7}, {%8,%9}, {%0,%1,%2,%3};"
        : "+f"(d0), "+f"(d1), "+f"(d2), "+f"(d3)
        : "r"(a0), "r"(a1), "r"(a2), "r"(a3), "r"(b0), "r"(b1));
}
__device__ __forceinline__ void ldsm_x4(uint32_t& r0, uint32_t& r1, uint32_t& r2,
                                        uint32_t& r3, uint32_t addr) {
    asm volatile("ldmatrix.sync.aligned.m8n8.x4.shared.b16 {%0,%1,%2,%3}, [%4];"
                 : "=r"(r0), "=r"(r1), "=r"(r2), "=r"(r3) : "r"(addr));
}
__device__ __forceinline__ void ldsm_x2t(uint32_t& r0, uint32_t& r1, uint32_t addr) {
    asm volatile("ldmatrix.sync.aligned.m8n8.x2.trans.shared.b16 {%0,%1}, [%2];"
                 : "=r"(r0), "=r"(r1) : "r"(addr));
}

// ---------------------------------------------------------------------------
// Prep: split W1/W2/Wt into bf16 hi/lo. 16 elements per thread.
// ---------------------------------------------------------------------------
__global__ void __launch_bounds__(256)
k_prep(const float* __restrict__ W1, const float* __restrict__ W2,
       const float* __restrict__ Wt)
{
    int i = blockIdx.x * 256 + threadIdx.x;          // one per 16-col group
    if (i >= WROWS * (TOK / 16)) return;
    int row = i >> 8;                                // 256 groups per row
    int c16 = (i & 255) << 4;

    const float* src = nullptr;
    if (row < 176)      { if (row < 172)            src = W1 + (size_t)row * TOK + c16; }
    else if (row < 352) { int k = row - 176; if (k < 172) src = W2 + (size_t)k * TOK + c16; }
    else                { int k = row - 352; if (k < 100) src = Wt + (size_t)k * TOK + c16; }

    float v[16];
#pragma unroll
    for (int j = 0; j < 16; j++) v[j] = 0.f;
    if (src) {
#pragma unroll
        for (int q = 0; q < 4; q++) {
            float4 a = __ldg((const float4*)(src + 4 * q));
            v[4 * q] = a.x; v[4 * q + 1] = a.y; v[4 * q + 2] = a.z; v[4 * q + 3] = a.w;
        }
    }
    __align__(16) __nv_bfloat16 h[16], l[16];
#pragma unroll
    for (int j = 0; j < 16; j++) {
        h[j] = __float2bfloat16(v[j]);
        l[j] = __float2bfloat16(v[j] - __bfloat162float(h[j]));
    }
    *(uint4*)(g_wh + (size_t)row * TOK + c16)     = ((uint4*)h)[0];
    *(uint4*)(g_wh + (size_t)row * TOK + c16 + 8) = ((uint4*)h)[1];
    *(uint4*)(g_wl + (size_t)row * TOK + c16)     = ((uint4*)l)[0];
    *(uint4*)(g_wl + (size_t)row * TOK + c16 + 8) = ((uint4*)l)[1];
}

// ---------------------------------------------------------------------------
// Proj smem layout (bytes):
//   A region [0, 24064):
//     G1/G2: A1h@0, A1l@5888, A2h@11776, A2l@17664 (16x184 bf16, 368B rows)
//     G3 (reuse): Th@0, Tl@7680 (32x120 bf16, 240B rows)
//   3 W stages @24064: each = [hi 16x528B][lo 16x528B] = 16896 B
// ---------------------------------------------------------------------------
#define A_REGION_B 24064
#define WS_ROW_B   528
#define WSTG_B     (2 * 16 * WS_ROW_B)               // 16896
#define SMEMP_B    (A_REGION_B + 3 * WSTG_B)         // 74752 -> 2 CTAs/SM, single wave

__device__ __forceinline__ void fill_wstage(char* stg, int krow0, int col0, int tid)
{
#pragma unroll
    for (int j = 0; j < 4; j++) {
        int c   = tid + 256 * j;            // 0..1023
        int mat = c >> 9;                   // 0 = hi, 1 = lo
        int r   = (c >> 5) & 15;
        int c16 = c & 31;
        const __nv_bfloat16* src = (mat ? g_wl : g_wh)
                                 + (size_t)(krow0 + r) * TOK + col0 + c16 * 8;
        cp16(s2u(stg + mat * (16 * WS_ROW_B) + r * WS_ROW_B + c16 * 16), src);
    }
}

// One GEMM: MT m16-tiles, NSTEP k16-steps, 3-deep cp.async pipeline.
template<int MT, int NSTEP>
__device__ __forceinline__ void run_gemm(
    char* s0, char* s1, char* s2,
    uint32_t aH, uint32_t aL, int astride_b,
    int wrow0, int col0, int b, int orow0, int nvalid,
    const float* __restrict__ bias, int tid)
{
    char* stgs[3] = {s0, s1, s2};
    const int lane = tid & 31;
    const int wid  = tid >> 5;
    const int n0   = wid * 32;
    const int g    = lane >> 2;
    const int tg   = lane & 3;
    const int arow = lane & 15;
    const int acol = (lane >> 4) << 3;
    const int brow = lane & 15;

    float acc[MT][4][4];
#pragma unroll
    for (int mt = 0; mt < MT; mt++)
#pragma unroll
        for (int j = 0; j < 4; j++)
#pragma unroll
            for (int q = 0; q < 4; q++) acc[mt][j][q] = 0.f;

    fill_wstage(stgs[0], wrow0, col0, tid);
    cp_commit();
    fill_wstage(stgs[1], wrow0 + 16, col0, tid);
    cp_commit();

    for (int s = 0; s < NSTEP; s++) {
        if (s + 2 < NSTEP) {
            int slot = s + 2; while (slot >= 3) slot -= 3;
            fill_wstage(stgs[slot], wrow0 + (s + 2) * 16, col0, tid);
            cp_commit();
            cp_wait<2>();
        } else if (s + 1 < NSTEP) {
            cp_wait<1>();
        } else {
            cp_wait<0>();
        }
        __syncthreads();

        int cur = s; while (cur >= 3) cur -= 3;
        const uint32_t st_s = s2u(stgs[cur]);
        const int k0 = s * 16;

        uint32_t bh[4][2], bl[4][2];
#pragma unroll
        for (int j = 0; j < 4; j++) {
            uint32_t baddr = st_s + brow * WS_ROW_B + (n0 + j * 8) * 2;
            ldsm_x2t(bh[j][0], bh[j][1], baddr);
            ldsm_x2t(bl[j][0], bl[j][1], baddr + 16 * WS_ROW_B);
        }
#pragma unroll
        for (int mt = 0; mt < MT; mt++) {
            uint32_t ah0, ah1, ah2, ah3, al0, al1, al2, al3;
            ldsm_x4(ah0, ah1, ah2, ah3,
                    aH + (mt * 16 + arow) * astride_b + (k0 + acol) * 2);
            ldsm_x4(al0, al1, al2, al3,
                    aL + (mt * 16 + arow) * astride_b + (k0 + acol) * 2);
#pragma unroll
            for (int j = 0; j < 4; j++) {
                mma_bf16(acc[mt][j][0], acc[mt][j][1], acc[mt][j][2], acc[mt][j][3],
                         ah0, ah1, ah2, ah3, bh[j][0], bh[j][1]);
                mma_bf16(acc[mt][j][0], acc[mt][j][1], acc[mt][j][2], acc[mt][j][3],
                         ah0, ah1, ah2, ah3, bl[j][0], bl[j][1]);
                mma_bf16(acc[mt][j][0], acc[mt][j][1], acc[mt][j][2], acc[mt][j][3],
                         al0, al1, al2, al3, bh[j][0], bh[j][1]);
            }
        }
        __syncthreads();
    }

    // writeback with bias
    float* base = g_res + ((size_t)b * NROWS + orow0) * TOK + col0;
#pragma unroll
    for (int mt = 0; mt < MT; mt++) {
        const int r0 = mt * 16 + g;
#pragma unroll
        for (int j = 0; j < 4; j++) {
            const int c = n0 + j * 8 + tg * 2;
            float bv0 = __ldg(&bias[col0 + c]);
            float bv1 = __ldg(&bias[col0 + c + 1]);
            if (r0 < nvalid) {
                float2 v = make_float2(acc[mt][j][0] + bv0, acc[mt][j][1] + bv1);
                *(float2*)(base + (size_t)r0 * TOK + c) = v;
            }
            if (r0 + 8 < nvalid) {
                float2 v = make_float2(acc[mt][j][2] + bv0, acc[mt][j][3] + bv1);
                *(float2*)(base + (size_t)(r0 + 8) * TOK + c) = v;
            }
        }
    }
}

// ---------------------------------------------------------------------------
// Proj: grid (16 batches, 16 n-tiles of 256 cols) = 256 CTAs, block 256.
// At 74.8 KB smem -> 2 CTAs/SM -> capacity 296 -> single wave.
// ---------------------------------------------------------------------------
__global__ void __launch_bounds__(256)
k_proj(const float* __restrict__ memory,
       const int*   __restrict__ src_nodes,
       const int*   __restrict__ dst_nodes,
       const int*   __restrict__ src_nei,
       const int*   __restrict__ dst_nei,
       const float* __restrict__ timestamps,
       const float* __restrict__ se,
       const float* __restrict__ de,
       const float* __restrict__ b1,
       const float* __restrict__ b2,
       const float* __restrict__ bt,
       const float* __restrict__ w_time,
       const float* __restrict__ phase)
{
    extern __shared__ __align__(16) char sm[];
    char* Areg = sm;
    char* s0 = sm + A_REGION_B;
    char* s1 = s0 + WSTG_B;
    char* s2 = s1 + WSTG_B;

    const int b    = blockIdx.x;
    const int tile = blockIdx.y;
    const int col0 = tile * 256;
    const int tid  = threadIdx.x;

    // ---- stage A1/A2 hi/lo (16 rows x 176 cols each, pad rows/cols zero) ----
    for (int i = tid; i < 2 * 16 * 176; i += 256) {
        int m = i / (16 * 176);
        int r = (i / 176) & 15;
        int k = i % 176;
        float a = 0.f;
        if (r < 11 && k < 172) {
            int node;
            if (m == 0) node = (r == 0) ? src_nodes[b] : dst_nei[b * 10 + r - 1];
            else        node = (r == 0) ? dst_nodes[b] : src_nei[b * 10 + r - 1];
            a = memory[(size_t)node * MEM_DIM + k];
        }
        __nv_bfloat16 h = __float2bfloat16(a);
        __nv_bfloat16 l = __float2bfloat16(a - __bfloat162float(h));
        __nv_bfloat16* Ah = (__nv_bfloat16*)(Areg + m * 11776);
        __nv_bfloat16* Al = (__nv_bfloat16*)(Areg + m * 11776 + 5888);
        Ah[r * 184 + k] = h;
        Al[r * 184 + k] = l;
    }
    // (sync provided by first in-loop barrier of G1)

    const uint32_t A1h = s2u(Areg), A1l = s2u(Areg + 5888);
    const uint32_t A2h = s2u(Areg + 11776), A2l = s2u(Areg + 17664);

    run_gemm<1, 11>(s0, s1, s2, A1h, A1l, 368, 0,   col0, b, 0,  11, b1, tid);
    run_gemm<1, 11>(s0, s1, s2, A2h, A2l, 368, 176, col0, b, 11, 11, b2, tid);

    // ---- stage tenc hi/lo (32 rows x 112 cols; rows>=21, cols>=100 zero) ----
    __syncthreads();
    const float t0 = timestamps[b];
    for (int i = tid; i < 32 * 112; i += 256) {
        int r = i / 112;
        int k = i % 112;
        float v = 0.f;
        if (r < 21 && k < 100) {
            float delta;
            if (r == 0)      delta = 0.f;
            else if (r < 11) delta = t0 - se[b * 10 + r - 1];
            else             delta = t0 - de[b * 10 + r - 11];
            v = cosf(delta * w_time[k] + phase[k]);
        }
        __nv_bfloat16 h = __float2bfloat16(v);
        __nv_bfloat16 l = __float2bfloat16(v - __bfloat162float(h));
        ((__nv_bfloat16*)Areg)[r * 120 + k] = h;
        ((__nv_bfloat16*)(Areg + 7680))[r * 120 + k] = l;
    }

    const uint32_t Th = s2u(Areg), Tl = s2u(Areg + 7680);
    run_gemm<2, 7>(s0, s1, s2, Th, Tl, 240, 352, col0, b, 22, 21, bt, tid);
}

// ---------------------------------------------------------------------------
// Scat (proven): grid (16 b, 16 tiles of 256 cols, 25 runs), block 256.
// ---------------------------------------------------------------------------
__global__ void __launch_bounds__(256)
k_scat(float* __restrict__ out)
{
    const int b    = blockIdx.x;
    const int tile = blockIdx.y;
    const int z    = blockIdx.z;
    const int tid  = threadIdx.x;
    const int lane = tid & 63;
    const int sub  = tid >> 6;

    int t0, n, rS, rD, rT;
    if (z < 10)       { t0 = 15 + 21 * z;  n = 21; rS = 0;  rD = 12 + z; rT = 23 + z; }
    else if (z < 20)  { int q = z - 10; t0 = 239 + 21 * q; n = 21; rS = 11; rD = 1 + q; rT = 33 + q; }
    else if (z == 20) { t0 = 0;   n = 15; rS = 0;  rD = 11; rT = 22; }
    else if (z == 21) { t0 = 225; n = 14; rS = 11; rD = 11; rT = 22; }
    else              { t0 = 449 + 21 * (z - 22); n = 21; rS = 0; rD = 11; rT = 22; }

    const float4* gresv = (const float4*)g_res;
    const int vrow = TOK / 4;
    const size_t rbase = (size_t)b * NROWS * vrow + tile * 64 + lane;
    const float4 vs = __ldg(&gresv[rbase + (size_t)rS * vrow]);
    const float4 vd = __ldg(&gresv[rbase + (size_t)rD * vrow]);
    const float4 vt = __ldg(&gresv[rbase + (size_t)rT * vrow]);

    float4* outv = (float4*)out;
    const size_t T = (size_t)BATCH * LEN_TOK * vrow;
    const size_t obase = (size_t)(b * LEN_TOK) * vrow + tile * 64 + lane;

    if (z == 20) {
        for (int i = sub; i < n; i += 4) {
            const int t = t0 + i;
            const size_t o = obase + (size_t)t * vrow;
            __stcs(&outv[o],         vs);
            __stcs(&outv[o + T],     (t == 0) ? vd : vs);
            __stcs(&outv[o + 2 * T], vt);
        }
    } else {
        for (int i = sub; i < n; i += 4) {
            const size_t o = obase + (size_t)(t0 + i) * vrow;
            __stcs(&outv[o],         vs);
            __stcs(&outv[o + T],     vd);
            __stcs(&outv[o + 2 * T], vt);
        }
    }
}

// ---------------------------------------------------------------------------
extern "C" void kernel_launch(void* const* d_in, const int* in_sizes, int n_in,
                              void* d_out, int out_size)
{
    const float* memory      = (const float*)d_in[0];
    const int*   src_nodes   = (const int*)  d_in[1];
    const int*   dst_nodes   = (const int*)  d_in[2];
    const int*   src_nei     = (const int*)  d_in[3];
    const int*   dst_nei     = (const int*)  d_in[4];
    const float* timestamps  = (const float*)d_in[5];
    const float* se          = (const float*)d_in[6];
    const float* de          = (const float*)d_in[7];
    const float* W1          = (const float*)d_in[8];
    const float* b1          = (const float*)d_in[9];
    const float* W2          = (const float*)d_in[10];
    const float* b2          = (const float*)d_in[11];
    const float* Wt          = (const float*)d_in[12];
    const float* bt          = (const float*)d_in[13];
    const float* w_time      = (const float*)d_in[14];
    const float* phase       = (const float*)d_in[15];
    float* out = (float*)d_out;

    cudaFuncSetAttribute(k_proj, cudaFuncAttributeMaxDynamicSharedMemorySize, SMEMP_B);

    k_prep<<<(WROWS * (TOK / 16) + 255) / 256, 256>>>(W1, W2, Wt);
    k_proj<<<dim3(BATCH, TOK / 256), 256, SMEMP_B>>>(memory, src_nodes, dst_nodes,
                                                     src_nei, dst_nei,
                                                     timestamps, se, de,
                                                     b1, b2, bt, w_time, phase);
    k_scat<<<dim3(BATCH, TOK / 256, 25), 256>>>(out);
}

// round 15
// speedup vs baseline: 1.0576x; 1.0036x over previous
#include <cuda_runtime.h>
#include <cuda_bf16.h>
#include <math.h>
#include <stdint.h>

#define BATCH     16
#define MEM_DIM   172
#define TOK       4096
#define TIME_DIM  100
#define LEN_TOK   512
#define NROWS     44

// g_wh/g_wl row layout: [0,176) = W1 (pad rows 0), [176,352) = W2, [352,464) = Wt
#define WROWS     464

__device__ __align__(16) __nv_bfloat16 g_wh[WROWS * TOK];
__device__ __align__(16) __nv_bfloat16 g_wl[WROWS * TOK];
__device__ __align__(16) float g_res[BATCH * NROWS * TOK];

// ---------------------------------------------------------------------------
__device__ __forceinline__ uint32_t s2u(const void* p) {
    return (uint32_t)__cvta_generic_to_shared(p);
}
__device__ __forceinline__ void cp16(uint32_t dst, const void* src) {
    asm volatile("cp.async.cg.shared.global [%0], [%1], 16;" :: "r"(dst), "l"(src));
}
__device__ __forceinline__ void cp_commit() { asm volatile("cp.async.commit_group;"); }
template<int N> __device__ __forceinline__ void cp_wait() {
    asm volatile("cp.async.wait_group %0;" :: "n"(N) : "memory");
}
__device__ __forceinline__ void mma_bf16(float& d0, float& d1, float& d2, float& d3,
                                         uint32_t a0, uint32_t a1, uint32_t a2, uint32_t a3,
                                         uint32_t b0, uint32_t b1)
{
    asm volatile(
        "mma.sync.aligned.m16n8k16.row.col.f32.bf16.bf16.f32 "
        "{%0,%1,%2,%3}, {%4,%5,%6,%7}, {%8,%9}, {%0,%1,%2,%3};"
        : "+f"(d0), "+f"(d1), "+f"(d2), "+f"(d3)
        : "r"(a0), "r"(a1), "r"(a2), "r"(a3), "r"(b0), "r"(b1));
}
__device__ __forceinline__ void ldsm_x4(uint32_t& r0, uint32_t& r1, uint32_t& r2,
                                        uint32_t& r3, uint32_t addr) {
    asm volatile("ldmatrix.sync.aligned.m8n8.x4.shared.b16 {%0,%1,%2,%3}, [%4];"
                 : "=r"(r0), "=r"(r1), "=r"(r2), "=r"(r3) : "r"(addr));
}
__device__ __forceinline__ void ldsm_x2t(uint32_t& r0, uint32_t& r1, uint32_t addr) {
    asm volatile("ldmatrix.sync.aligned.m8n8.x2.trans.shared.b16 {%0,%1}, [%2];"
                 : "=r"(r0), "=r"(r1) : "r"(addr));
}

// ---------------------------------------------------------------------------
// Prep: split W1/W2/Wt into bf16 hi/lo. 4 elements per thread (fine grain).
// ---------------------------------------------------------------------------
__global__ void __launch_bounds__(256)
k_prep(const float* __restrict__ W1, const float* __restrict__ W2,
       const float* __restrict__ Wt)
{
    int i = blockIdx.x * 256 + threadIdx.x;          // one per 4-col group
    if (i >= WROWS * (TOK / 4)) return;
    int row = i >> 10;                               // 1024 groups per row
    int c4  = (i & 1023) << 2;

    const float* src = nullptr;
    if (row < 176)      { if (row < 172)            src = W1 + (size_t)row * TOK + c4; }
    else if (row < 352) { int k = row - 176; if (k < 172) src = W2 + (size_t)k * TOK + c4; }
    else                { int k = row - 352; if (k < 100) src = Wt + (size_t)k * TOK + c4; }

    float v[4] = {0.f, 0.f, 0.f, 0.f};
    if (src) {
        float4 a = __ldg((const float4*)src);
        v[0] = a.x; v[1] = a.y; v[2] = a.z; v[3] = a.w;
    }
    __align__(8) __nv_bfloat16 h[4], l[4];
#pragma unroll
    for (int j = 0; j < 4; j++) {
        h[j] = __float2bfloat16(v[j]);
        l[j] = __float2bfloat16(v[j] - __bfloat162float(h[j]));
    }
    *(uint2*)(g_wh + (size_t)row * TOK + c4) = *(uint2*)h;
    *(uint2*)(g_wl + (size_t)row * TOK + c4) = *(uint2*)l;
}

// ---------------------------------------------------------------------------
// Proj smem layout (bytes):
//   A region [0, 24064):
//     G1/G2: A1h@0, A1l@5888, A2h@11776, A2l@17664 (16x184 bf16, 368B rows)
//     G3 (reuse): Th@0, Tl@7680 (32x120 bf16, 240B rows)
//   3 W stages @24064: each = [hi 16x528B][lo 16x528B] = 16896 B
// ---------------------------------------------------------------------------
#define A_REGION_B 24064
#define WS_ROW_B   528
#define WSTG_B     (2 * 16 * WS_ROW_B)               // 16896
#define SMEMP_B    (A_REGION_B + 3 * WSTG_B)         // 74752

#define NTHREADS   512                               // 16 warps, 16 cols/warp

__device__ __forceinline__ void fill_wstage(char* stg, int krow0, int col0, int tid)
{
#pragma unroll
    for (int j = 0; j < 2; j++) {
        int c   = tid + NTHREADS * j;       // 0..1023
        int mat = c >> 9;                   // 0 = hi, 1 = lo
        int r   = (c >> 5) & 15;
        int c16 = c & 31;
        const __nv_bfloat16* src = (mat ? g_wl : g_wh)
                                 + (size_t)(krow0 + r) * TOK + col0 + c16 * 8;
        cp16(s2u(stg + mat * (16 * WS_ROW_B) + r * WS_ROW_B + c16 * 16), src);
    }
}

// One GEMM: MT m16-tiles, NSTEP k16-steps, 3-deep cp.async pipeline.
// 16 warps, each owning 16 output columns (2 n8-tiles).
template<int MT, int NSTEP>
__device__ __forceinline__ void run_gemm(
    char* s0, char* s1, char* s2,
    uint32_t aH, uint32_t aL, int astride_b,
    int wrow0, int col0, int b, int orow0, int nvalid,
    const float* __restrict__ bias, int tid)
{
    char* stgs[3] = {s0, s1, s2};
    const int lane = tid & 31;
    const int wid  = tid >> 5;              // 0..15
    const int n0   = wid * 16;
    const int g    = lane >> 2;
    const int tg   = lane & 3;
    const int arow = lane & 15;
    const int acol = (lane >> 4) << 3;
    const int brow = lane & 15;

    float acc[MT][2][4];
#pragma unroll
    for (int mt = 0; mt < MT; mt++)
#pragma unroll
        for (int j = 0; j < 2; j++)
#pragma unroll
            for (int q = 0; q < 4; q++) acc[mt][j][q] = 0.f;

    fill_wstage(stgs[0], wrow0, col0, tid);
    cp_commit();
    fill_wstage(stgs[1], wrow0 + 16, col0, tid);
    cp_commit();

    for (int s = 0; s < NSTEP; s++) {
        if (s + 2 < NSTEP) {
            int slot = s + 2; while (slot >= 3) slot -= 3;
            fill_wstage(stgs[slot], wrow0 + (s + 2) * 16, col0, tid);
            cp_commit();
            cp_wait<2>();
        } else if (s + 1 < NSTEP) {
            cp_wait<1>();
        } else {
            cp_wait<0>();
        }
        __syncthreads();

        int cur = s; while (cur >= 3) cur -= 3;
        const uint32_t st_s = s2u(stgs[cur]);
        const int k0 = s * 16;

        uint32_t bh[2][2], bl[2][2];
#pragma unroll
        for (int j = 0; j < 2; j++) {
            uint32_t baddr = st_s + brow * WS_ROW_B + (n0 + j * 8) * 2;
            ldsm_x2t(bh[j][0], bh[j][1], baddr);
            ldsm_x2t(bl[j][0], bl[j][1], baddr + 16 * WS_ROW_B);
        }
#pragma unroll
        for (int mt = 0; mt < MT; mt++) {
            uint32_t ah0, ah1, ah2, ah3, al0, al1, al2, al3;
            ldsm_x4(ah0, ah1, ah2, ah3,
                    aH + (mt * 16 + arow) * astride_b + (k0 + acol) * 2);
            ldsm_x4(al0, al1, al2, al3,
                    aL + (mt * 16 + arow) * astride_b + (k0 + acol) * 2);
#pragma unroll
            for (int j = 0; j < 2; j++) {
                mma_bf16(acc[mt][j][0], acc[mt][j][1], acc[mt][j][2], acc[mt][j][3],
                         ah0, ah1, ah2, ah3, bh[j][0], bh[j][1]);
                mma_bf16(acc[mt][j][0], acc[mt][j][1], acc[mt][j][2], acc[mt][j][3],
                         ah0, ah1, ah2, ah3, bl[j][0], bl[j][1]);
                mma_bf16(acc[mt][j][0], acc[mt][j][1], acc[mt][j][2], acc[mt][j][3],
                         al0, al1, al2, al3, bh[j][0], bh[j][1]);
            }
        }
        __syncthreads();
    }

    // writeback with bias
    float* base = g_res + ((size_t)b * NROWS + orow0) * TOK + col0;
#pragma unroll
    for (int mt = 0; mt < MT; mt++) {
        const int r0 = mt * 16 + g;
#pragma unroll
        for (int j = 0; j < 2; j++) {
            const int c = n0 + j * 8 + tg * 2;
            float bv0 = __ldg(&bias[col0 + c]);
            float bv1 = __ldg(&bias[col0 + c + 1]);
            if (r0 < nvalid) {
                float2 v = make_float2(acc[mt][j][0] + bv0, acc[mt][j][1] + bv1);
                *(float2*)(base + (size_t)r0 * TOK + c) = v;
            }
            if (r0 + 8 < nvalid) {
                float2 v = make_float2(acc[mt][j][2] + bv0, acc[mt][j][3] + bv1);
                *(float2*)(base + (size_t)(r0 + 8) * TOK + c) = v;
            }
        }
    }
}

// ---------------------------------------------------------------------------
// Proj: grid (16 batches, 16 n-tiles of 256 cols) = 256 CTAs, block 512.
// ---------------------------------------------------------------------------
__global__ void __launch_bounds__(NTHREADS)
k_proj(const float* __restrict__ memory,
       const int*   __restrict__ src_nodes,
       const int*   __restrict__ dst_nodes,
       const int*   __restrict__ src_nei,
       const int*   __restrict__ dst_nei,
       const float* __restrict__ timestamps,
       const float* __restrict__ se,
       const float* __restrict__ de,
       const float* __restrict__ b1,
       const float* __restrict__ b2,
       const float* __restrict__ bt,
       const float* __restrict__ w_time,
       const float* __restrict__ phase)
{
    extern __shared__ __align__(16) char sm[];
    char* Areg = sm;
    char* s0 = sm + A_REGION_B;
    char* s1 = s0 + WSTG_B;
    char* s2 = s1 + WSTG_B;

    const int b    = blockIdx.x;
    const int tile = blockIdx.y;
    const int col0 = tile * 256;
    const int tid  = threadIdx.x;

    // ---- stage A1/A2 hi/lo (16 rows x 176 cols each, pad rows/cols zero) ----
    for (int i = tid; i < 2 * 16 * 176; i += NTHREADS) {
        int m = i / (16 * 176);
        int r = (i / 176) & 15;
        int k = i % 176;
        float a = 0.f;
        if (r < 11 && k < 172) {
            int node;
            if (m == 0) node = (r == 0) ? src_nodes[b] : dst_nei[b * 10 + r - 1];
            else        node = (r == 0) ? dst_nodes[b] : src_nei[b * 10 + r - 1];
            a = memory[(size_t)node * MEM_DIM + k];
        }
        __nv_bfloat16 h = __float2bfloat16(a);
        __nv_bfloat16 l = __float2bfloat16(a - __bfloat162float(h));
        __nv_bfloat16* Ah = (__nv_bfloat16*)(Areg + m * 11776);
        __nv_bfloat16* Al = (__nv_bfloat16*)(Areg + m * 11776 + 5888);
        Ah[r * 184 + k] = h;
        Al[r * 184 + k] = l;
    }
    // (sync provided by first in-loop barrier of G1)

    const uint32_t A1h = s2u(Areg), A1l = s2u(Areg + 5888);
    const uint32_t A2h = s2u(Areg + 11776), A2l = s2u(Areg + 17664);

    run_gemm<1, 11>(s0, s1, s2, A1h, A1l, 368, 0,   col0, b, 0,  11, b1, tid);
    run_gemm<1, 11>(s0, s1, s2, A2h, A2l, 368, 176, col0, b, 11, 11, b2, tid);

    // ---- stage tenc hi/lo (32 rows x 112 cols; rows>=21, cols>=100 zero) ----
    __syncthreads();
    const float t0 = timestamps[b];
    for (int i = tid; i < 32 * 112; i += NTHREADS) {
        int r = i / 112;
        int k = i % 112;
        float v = 0.f;
        if (r < 21 && k < 100) {
            float delta;
            if (r == 0)      delta = 0.f;
            else if (r < 11) delta = t0 - se[b * 10 + r - 1];
            else             delta = t0 - de[b * 10 + r - 11];
            v = cosf(delta * w_time[k] + phase[k]);
        }
        __nv_bfloat16 h = __float2bfloat16(v);
        __nv_bfloat16 l = __float2bfloat16(v - __bfloat162float(h));
        ((__nv_bfloat16*)Areg)[r * 120 + k] = h;
        ((__nv_bfloat16*)(Areg + 7680))[r * 120 + k] = l;
    }

    const uint32_t Th = s2u(Areg), Tl = s2u(Areg + 7680);
    run_gemm<2, 7>(s0, s1, s2, Th, Tl, 240, 352, col0, b, 22, 21, bt, tid);
}

// ---------------------------------------------------------------------------
// Scat (proven): grid (16 b, 16 tiles of 256 cols, 25 runs), block 256.
// ---------------------------------------------------------------------------
__global__ void __launch_bounds__(256)
k_scat(float* __restrict__ out)
{
    const int b    = blockIdx.x;
    const int tile = blockIdx.y;
    const int z    = blockIdx.z;
    const int tid  = threadIdx.x;
    const int lane = tid & 63;
    const int sub  = tid >> 6;

    int t0, n, rS, rD, rT;
    if (z < 10)       { t0 = 15 + 21 * z;  n = 21; rS = 0;  rD = 12 + z; rT = 23 + z; }
    else if (z < 20)  { int q = z - 10; t0 = 239 + 21 * q; n = 21; rS = 11; rD = 1 + q; rT = 33 + q; }
    else if (z == 20) { t0 = 0;   n = 15; rS = 0;  rD = 11; rT = 22; }
    else if (z == 21) { t0 = 225; n = 14; rS = 11; rD = 11; rT = 22; }
    else              { t0 = 449 + 21 * (z - 22); n = 21; rS = 0; rD = 11; rT = 22; }

    const float4* gresv = (const float4*)g_res;
    const int vrow = TOK / 4;
    const size_t rbase = (size_t)b * NROWS * vrow + tile * 64 + lane;
    const float4 vs = __ldg(&gresv[rbase + (size_t)rS * vrow]);
    const float4 vd = __ldg(&gresv[rbase + (size_t)rD * vrow]);
    const float4 vt = __ldg(&gresv[rbase + (size_t)rT * vrow]);

    float4* outv = (float4*)out;
    const size_t T = (size_t)BATCH * LEN_TOK * vrow;
    const size_t obase = (size_t)(b * LEN_TOK) * vrow + tile * 64 + lane;

    if (z == 20) {
        for (int i = sub; i < n; i += 4) {
            const int t = t0 + i;
            const size_t o = obase + (size_t)t * vrow;
            __stcs(&outv[o],         vs);
            __stcs(&outv[o + T],     (t == 0) ? vd : vs);
            __stcs(&outv[o + 2 * T], vt);
        }
    } else {
        for (int i = sub; i < n; i += 4) {
            const size_t o = obase + (size_t)(t0 + i) * vrow;
            __stcs(&outv[o],         vs);
            __stcs(&outv[o + T],     vd);
            __stcs(&outv[o + 2 * T], vt);
        }
    }
}

// ---------------------------------------------------------------------------
extern "C" void kernel_launch(void* const* d_in, const int* in_sizes, int n_in,
                              void* d_out, int out_size)
{
    const float* memory      = (const float*)d_in[0];
    const int*   src_nodes   = (const int*)  d_in[1];
    const int*   dst_nodes   = (const int*)  d_in[2];
    const int*   src_nei     = (const int*)  d_in[3];
    const int*   dst_nei     = (const int*)  d_in[4];
    const float* timestamps  = (const float*)d_in[5];
    const float* se          = (const float*)d_in[6];
    const float* de          = (const float*)d_in[7];
    const float* W1          = (const float*)d_in[8];
    const float* b1          = (const float*)d_in[9];
    const float* W2          = (const float*)d_in[10];
    const float* b2          = (const float*)d_in[11];
    const float* Wt          = (const float*)d_in[12];
    const float* bt          = (const float*)d_in[13];
    const float* w_time      = (const float*)d_in[14];
    const float* phase       = (const float*)d_in[15];
    float* out = (float*)d_out;

    cudaFuncSetAttribute(k_proj, cudaFuncAttributeMaxDynamicSharedMemorySize, SMEMP_B);

    k_prep<<<(WROWS * (TOK / 4) + 255) / 256, 256>>>(W1, W2, Wt);
    k_proj<<<dim3(BATCH, TOK / 256), NTHREADS, SMEMP_B>>>(memory, src_nodes, dst_nodes,
                                                          src_nei, dst_nei,
                                                          timestamps, se, de,
                                                          b1, b2, bt, w_time, phase);
    k_scat<<<dim3(BATCH, TOK / 256, 25), 256>>>(out);
}